// round 12
// baseline (speedup 1.0000x reference)
#include <cuda_runtime.h>
#include <cuda_bf16.h>
#include <cstdint>

#define B_    32
#define T_    1024
#define N_    1024
#define D_    256
#define WIN_  100
#define TT_   64            // t per tile; 2 tiles per CTA
#define NTHREADS 512

#define KRB  528
#define VROW 528
#define PROW 272
#define PST  65

// phase-1 offsets
#define OFF_KH 0
#define OFF_KL (OFF_KH + 128*KRB)        //  67584
#define OFF_QH (OFF_KL + 128*KRB)        // 135168
#define OFF_QL (OFF_QH + 64*KRB)         // 168960
// phase-2 aliases
#define OFF_VH  0
#define OFF_VL  67584
#define OFF_PH  135168
#define OFF_PL  (OFF_PH + 64*PROW)       // 152576
#define OFF_PRT (OFF_PL + 64*PROW)       // 169984
#define SMEM_BYTES (OFF_PRT + 128*PST*4) // 203264

__device__ __forceinline__ uint32_t smem_u32(const void* p) {
    uint32_t a;
    asm("{ .reg .u64 t; cvta.to.shared.u64 t, %1; cvt.u32.u64 %0, t; }" : "=r"(a) : "l"(p));
    return a;
}
__device__ __forceinline__ void ldsm4(uint32_t& r0, uint32_t& r1, uint32_t& r2, uint32_t& r3,
                                      uint32_t addr) {
    asm volatile("ldmatrix.sync.aligned.m8n8.x4.shared.b16 {%0,%1,%2,%3}, [%4];"
                 : "=r"(r0), "=r"(r1), "=r"(r2), "=r"(r3) : "r"(addr));
}
__device__ __forceinline__ void ldsm4t(uint32_t& r0, uint32_t& r1, uint32_t& r2, uint32_t& r3,
                                       uint32_t addr) {
    asm volatile("ldmatrix.sync.aligned.m8n8.x4.trans.shared.b16 {%0,%1,%2,%3}, [%4];"
                 : "=r"(r0), "=r"(r1), "=r"(r2), "=r"(r3) : "r"(addr));
}
__device__ __forceinline__ void mma16816(float* d, const uint32_t* a, uint32_t b0, uint32_t b1) {
    asm volatile("mma.sync.aligned.m16n8k16.row.col.f32.bf16.bf16.f32 "
                 "{%0,%1,%2,%3}, {%4,%5,%6,%7}, {%8,%9}, {%0,%1,%2,%3};"
                 : "+f"(d[0]), "+f"(d[1]), "+f"(d[2]), "+f"(d[3])
                 : "r"(a[0]), "r"(a[1]), "r"(a[2]), "r"(a[3]), "r"(b0), "r"(b1));
}
__device__ __forceinline__ void split8(const float* f, uint32_t* h4, uint32_t* l4) {
    #pragma unroll
    for (int i = 0; i < 4; i++) {
        __nv_bfloat16 h0 = __float2bfloat16(f[2*i]), h1 = __float2bfloat16(f[2*i+1]);
        float r0 = f[2*i]   - __bfloat162float(h0);
        float r1 = f[2*i+1] - __bfloat162float(h1);
        __nv_bfloat16 l0 = __float2bfloat16(r0), l1 = __float2bfloat16(r1);
        h4[i] = (uint32_t)__bfloat16_as_ushort(h0) | ((uint32_t)__bfloat16_as_ushort(h1) << 16);
        l4[i] = (uint32_t)__bfloat16_as_ushort(l0) | ((uint32_t)__bfloat16_as_ushort(l1) << 16);
    }
}

__global__ __launch_bounds__(NTHREADS, 1)
void attn_main(const float* __restrict__ Q, const float* __restrict__ K,
               const float* __restrict__ V, const int* __restrict__ prev_arr,
               float* __restrict__ out_res, float* __restrict__ out_align,
               float* __restrict__ out_max)
{
    extern __shared__ __align__(128) char sm[];
    const uint32_t smb = smem_u32(sm);
    float* prT = (float*)(sm + OFF_PRT);

    const int b    = blockIdx.y;
    const int t0   = blockIdx.x * 128;       // CTA covers t in [t0, t0+128)
    const int tid  = threadIdx.x;
    const int warp = tid >> 5;
    const int lane = tid & 31;
    const int prev = prev_arr[b];

    const float* Qb = Q + ((size_t)b*T_ + t0) * D_;
    const float* Kw = K + ((size_t)b*N_ + prev) * D_;
    const float* Vw = V + ((size_t)b*N_ + prev) * D_;

    // ---- Load K (rows 0..99, zero-pad to 128): split-store Kh/Kl ----
    #pragma unroll
    for (int it = 0; it < 8; it++) {
        int idx = tid + NTHREADS * it;
        int j = idx >> 5, g = idx & 31;
        float f[8] = {0,0,0,0,0,0,0,0};
        if (j < WIN_) {
            const float* src = Kw + (size_t)j * D_ + 8*g;
            float4 a = *(const float4*)(src);
            float4 c = *(const float4*)(src + 4);
            f[0]=a.x; f[1]=a.y; f[2]=a.z; f[3]=a.w; f[4]=c.x; f[5]=c.y; f[6]=c.z; f[7]=c.w;
        }
        uint32_t h4[4], l4[4];
        split8(f, h4, l4);
        uint32_t off = (uint32_t)(j*KRB + 16*g);
        *(uint4*)(sm + OFF_KH + off) = make_uint4(h4[0],h4[1],h4[2],h4[3]);
        *(uint4*)(sm + OFF_KL + off) = make_uint4(l4[0],l4[1],l4[2],l4[3]);
    }
    // ---- Load Q tile A (rows 0..63): out_res copy + split ----
    #pragma unroll
    for (int it = 0; it < 4; it++) {
        int idx = tid + NTHREADS * it;
        int t = idx >> 5, g = idx & 31;
        const float* src = Qb + (size_t)t * D_ + 8*g;
        float4 a = *(const float4*)(src);
        float4 c = *(const float4*)(src + 4);
        float f[8] = {a.x,a.y,a.z,a.w,c.x,c.y,c.z,c.w};
        float* qdst = out_res + ((size_t)b*T_ + t0 + t) * (2*D_) + 256 + 8*g;
        *(float4*)(qdst)     = a;
        *(float4*)(qdst + 4) = c;
        uint32_t h4[4], l4[4];
        split8(f, h4, l4);
        uint32_t off = (uint32_t)(t*KRB + 16*g);
        *(uint4*)(sm + OFF_QH + off) = make_uint4(h4[0],h4[1],h4[2],h4[3]);
        *(uint4*)(sm + OFF_QL + off) = make_uint4(l4[0],l4[1],l4[2],l4[3]);
    }
    // ---- Prefetch Q tile B (rows 64..127) into regs; LDG hides under MMA A ----
    float4 qpre[8];
    #pragma unroll
    for (int it = 0; it < 4; it++) {
        int idx = tid + NTHREADS * it;
        int t = idx >> 5, g = idx & 31;
        const float* src = Qb + (size_t)(64 + t) * D_ + 8*g;
        qpre[2*it]   = *(const float4*)(src);
        qpre[2*it+1] = *(const float4*)(src + 4);
    }
    __syncthreads();

    const int mi  = warp & 3;
    const int nj0 = (warp >> 2) * 32;
    const uint32_t aOff = (uint32_t)((mi*16 + (lane & 15))*KRB + ((lane >> 4) & 1)*16);
    const int nB = nj0 + ((lane >> 4) & 1)*8 + (lane & 7);
    const uint32_t bOff = (uint32_t)(nB*KRB + ((lane >> 3) & 1)*16);
    const uint32_t aQh = smb + OFF_QH + aOff;
    const uint32_t aQl = smb + OFF_QL + aOff;
    const uint32_t bKh0 = smb + OFF_KH + bOff;
    const uint32_t bKl0 = smb + OFF_KL + bOff;

    float dacc[2][4][4];
    #pragma unroll
    for (int tl = 0; tl < 2; tl++)
        #pragma unroll
        for (int nt = 0; nt < 4; nt++)
            #pragma unroll
            for (int i = 0; i < 4; i++) dacc[tl][nt][i] = 0.f;

    // ---- QK MMA tile A ----
    #pragma unroll 1
    for (int term = 0; term < 3; term++) {
        uint32_t aB  = (term == 2) ? aQl : aQh;
        uint32_t bB0 = (term == 1) ? bKl0 : bKh0;
        uint32_t bB1 = bB0 + 16*KRB;
        #pragma unroll 4
        for (int ks = 0; ks < 16; ks++) {
            uint32_t a[4], b0[4], b1[4];
            ldsm4(a[0], a[1], a[2], a[3], aB + ks*32);
            ldsm4(b0[0], b0[1], b0[2], b0[3], bB0 + ks*32);
            ldsm4(b1[0], b1[1], b1[2], b1[3], bB1 + ks*32);
            mma16816(dacc[0][0], a, b0[0], b0[1]);
            mma16816(dacc[0][1], a, b0[2], b0[3]);
            mma16816(dacc[0][2], a, b1[0], b1[1]);
            mma16816(dacc[0][3], a, b1[2], b1[3]);
        }
    }
    __syncthreads();   // QA reads done -> QH/QL reusable

    // ---- Write Q tile B from prefetch regs: out_res copy + split ----
    #pragma unroll
    for (int it = 0; it < 4; it++) {
        int idx = tid + NTHREADS * it;
        int t = idx >> 5, g = idx & 31;
        float4 a = qpre[2*it], c = qpre[2*it+1];
        float f[8] = {a.x,a.y,a.z,a.w,c.x,c.y,c.z,c.w};
        float* qdst = out_res + ((size_t)b*T_ + t0 + 64 + t) * (2*D_) + 256 + 8*g;
        *(float4*)(qdst)     = a;
        *(float4*)(qdst + 4) = c;
        uint32_t h4[4], l4[4];
        split8(f, h4, l4);
        uint32_t off = (uint32_t)(t*KRB + 16*g);
        *(uint4*)(sm + OFF_QH + off) = make_uint4(h4[0],h4[1],h4[2],h4[3]);
        *(uint4*)(sm + OFF_QL + off) = make_uint4(l4[0],l4[1],l4[2],l4[3]);
    }
    __syncthreads();

    // ---- QK MMA tile B ----
    #pragma unroll 1
    for (int term = 0; term < 3; term++) {
        uint32_t aB  = (term == 2) ? aQl : aQh;
        uint32_t bB0 = (term == 1) ? bKl0 : bKh0;
        uint32_t bB1 = bB0 + 16*KRB;
        #pragma unroll 4
        for (int ks = 0; ks < 16; ks++) {
            uint32_t a[4], b0[4], b1[4];
            ldsm4(a[0], a[1], a[2], a[3], aB + ks*32);
            ldsm4(b0[0], b0[1], b0[2], b0[3], bB0 + ks*32);
            ldsm4(b1[0], b1[1], b1[2], b1[3], bB1 + ks*32);
            mma16816(dacc[1][0], a, b0[0], b0[1]);
            mma16816(dacc[1][1], a, b0[2], b0[3]);
            mma16816(dacc[1][2], a, b1[0], b1[1]);
            mma16816(dacc[1][3], a, b1[2], b1[3]);
        }
    }
    __syncthreads();   // K/Q smem fully dead -> phase-2 aliasing legal

    // ---- PV lane addresses (shared across tiles) ----
    const int d0g = (warp >> 2) * 64;
    const uint32_t aPOff = (uint32_t)((mi*16 + (lane & 15))*PROW + ((lane >> 4) & 1)*16);
    const uint32_t bVOff = (uint32_t)((lane & 15)*VROW + d0g*2 + ((lane >> 4) & 1)*16);
    const uint32_t aPH = smb + OFF_PH + aPOff;
    const uint32_t aPL = smb + OFF_PL + aPOff;
    const uint32_t bVH = smb + OFF_VH + bVOff;
    const uint32_t bVL = smb + OFF_VL + bVOff;

    #pragma unroll 1
    for (int tile = 0; tile < 2; tile++) {
        const int tbase = t0 + tile*64;

        // ---- scores -> prT[j][t] (scaled) ----
        {
            const float s = 0.0625f;
            int tb = mi*16 + (lane >> 2);
            int jb = nj0 + (lane & 3)*2;
            if (tile == 0) {
                #pragma unroll
                for (int nt = 0; nt < 4; nt++) {
                    int j = jb + nt*8;
                    prT[(j  )*PST + tb    ] = dacc[0][nt][0] * s;
                    prT[(j+1)*PST + tb    ] = dacc[0][nt][1] * s;
                    prT[(j  )*PST + tb + 8] = dacc[0][nt][2] * s;
                    prT[(j+1)*PST + tb + 8] = dacc[0][nt][3] * s;
                }
            } else {
                #pragma unroll
                for (int nt = 0; nt < 4; nt++) {
                    int j = jb + nt*8;
                    prT[(j  )*PST + tb    ] = dacc[1][nt][0] * s;
                    prT[(j+1)*PST + tb    ] = dacc[1][nt][1] * s;
                    prT[(j  )*PST + tb + 8] = dacc[1][nt][2] * s;
                    prT[(j+1)*PST + tb + 8] = dacc[1][nt][3] * s;
                }
            }
        }
        __syncthreads();

        // ---- softmax (+ tile0: V load / zero-fill on warps 8-15) ----
        const int nsm = (tile == 0) ? 8 : 16;          // softmax warps
        if (warp < nsm) {
            const int rows = 64 / nsm;
            const int trow = warp * rows;
            #pragma unroll
            for (int tt = 0; tt < 8; tt++) {
                if (tt >= rows) break;
                int t = trow + tt;
                float v_[4];
                #pragma unroll
                for (int i = 0; i < 4; i++) v_[i] = prT[(lane + 32*i)*PST + t];

                float mx = -3.4e38f;
                #pragma unroll
                for (int i = 0; i < 4; i++)
                    if (lane + 32*i < WIN_) mx = fmaxf(mx, v_[i]);
                #pragma unroll
                for (int off = 16; off; off >>= 1)
                    mx = fmaxf(mx, __shfl_xor_sync(0xffffffffu, mx, off));

                float e_[4]; float s = 0.f;
                #pragma unroll
                for (int i = 0; i < 4; i++) {
                    e_[i] = (lane + 32*i < WIN_) ? __expf(v_[i] - mx) : 0.f;
                    s += e_[i];
                }
                #pragma unroll
                for (int off = 16; off; off >>= 1)
                    s += __shfl_xor_sync(0xffffffffu, s, off);
                float inv = 1.f / s;

                float pr[4];
                #pragma unroll
                for (int i = 0; i < 4; i++) pr[i] = e_[i] * inv;

                float bm = -1.f; int bi = N_;
                #pragma unroll
                for (int i = 0; i < 4; i++)
                    if (pr[i] > bm) { bm = pr[i]; bi = lane + 32*i; }
                #pragma unroll
                for (int off = 16; off; off >>= 1) {
                    float om = __shfl_xor_sync(0xffffffffu, bm, off);
                    int   oi = __shfl_xor_sync(0xffffffffu, bi, off);
                    if (om > bm || (om == bm && oi < bi)) { bm = om; bi = oi; }
                }
                if (lane == 0)
                    out_max[(size_t)b*T_ + tbase + t] = (float)(prev + bi);

                #pragma unroll
                for (int i = 0; i < 4; i++) {
                    int j = lane + 32*i;
                    prT[j*PST + t] = pr[i];
                    __nv_bfloat16 ph = __float2bfloat16(pr[i]);
                    float rl = pr[i] - __bfloat162float(ph);
                    __nv_bfloat16 pl = __float2bfloat16(rl);
                    *(__nv_bfloat16*)(sm + OFF_PH + t*PROW + 2*j) = ph;
                    *(__nv_bfloat16*)(sm + OFF_PL + t*PROW + 2*j) = pl;
                }
            }
        } else if (tile == 0) {
            // warps 8..15: V load+split (over KH/KL) + 128-wide zero-fill
            const int ltid = tid - 256;
            #pragma unroll
            for (int it = 0; it < 16; it++) {
                int idx = ltid + 256 * it;
                int j = idx >> 5, g = idx & 31;
                float f[8] = {0,0,0,0,0,0,0,0};
                if (j < WIN_) {
                    const float* src = Vw + (size_t)j * D_ + 8*g;
                    float4 a = *(const float4*)(src);
                    float4 c = *(const float4*)(src + 4);
                    f[0]=a.x; f[1]=a.y; f[2]=a.z; f[3]=a.w; f[4]=c.x; f[5]=c.y; f[6]=c.z; f[7]=c.w;
                }
                uint32_t h4[4], l4[4];
                split8(f, h4, l4);
                uint32_t off = (uint32_t)(j*VROW + 16*g);
                *(uint4*)(sm + OFF_VH + off) = make_uint4(h4[0],h4[1],h4[2],h4[3]);
                *(uint4*)(sm + OFF_VL + off) = make_uint4(l4[0],l4[1],l4[2],l4[3]);
            }
            // zero-fill: warp owns full 512B row via STG.128
            #pragma unroll 1
            for (int r = warp - 8; r < N_; r += 8) {
                if (r >= prev && r < prev + WIN_) continue;
                float* ar = out_align + ((size_t)b*N_ + r)*T_ + t0;
                *(float4*)(ar + lane*4) = make_float4(0.f,0.f,0.f,0.f);
            }
        }
        __syncthreads();

        // ---- alignments band (this tile's 64 cols) ----
        #pragma unroll 1
        for (int j = warp; j < WIN_; j += 16) {
            float* ar = out_align + ((size_t)b*N_ + prev + j)*T_ + tbase;
            ar[lane]      = prT[j*PST + lane];
            ar[32 + lane] = prT[j*PST + 32 + lane];
        }

        // ---- PV via HMMA ----
        {
            float oacc[8][4];
            #pragma unroll
            for (int nt = 0; nt < 8; nt++)
                #pragma unroll
                for (int i = 0; i < 4; i++) oacc[nt][i] = 0.f;

            #pragma unroll 1
            for (int term = 0; term < 3; term++) {
                uint32_t aB = (term == 2) ? aPL : aPH;
                uint32_t bB = (term == 1) ? bVL : bVH;
                #pragma unroll 2
                for (int ks = 0; ks < 8; ks++) {
                    uint32_t a[4];
                    ldsm4(a[0], a[1], a[2], a[3], aB + ks*32);
                    uint32_t bRow = bB + ks*(16*VROW);
                    #pragma unroll
                    for (int np = 0; np < 4; np++) {
                        uint32_t bb[4];
                        ldsm4t(bb[0], bb[1], bb[2], bb[3], bRow + np*32);
                        mma16816(oacc[2*np],   a, bb[0], bb[1]);
                        mma16816(oacc[2*np+1], a, bb[2], bb[3]);
                    }
                }
            }
            int tr = mi*16 + (lane >> 2);
            int dc = (lane & 3)*2;
            #pragma unroll
            for (int nt = 0; nt < 8; nt++) {
                int d = d0g + nt*8 + dc;
                float* o0 = out_res + ((size_t)b*T_ + tbase + tr    )*(2*D_) + d;
                float* o1 = out_res + ((size_t)b*T_ + tbase + tr + 8)*(2*D_) + d;
                *(float2*)o0 = make_float2(oacc[nt][0], oacc[nt][1]);
                *(float2*)o1 = make_float2(oacc[nt][2], oacc[nt][3]);
            }
        }
        __syncthreads();   // prT/PH/PL reads done before next tile overwrites
    }
}

extern "C" void kernel_launch(void* const* d_in, const int* in_sizes, int n_in,
                              void* d_out, int out_size)
{
    const float* Q    = (const float*)d_in[0];
    const float* K    = (const float*)d_in[1];
    const float* V    = (const float*)d_in[2];
    const int*   prev = (const int*)d_in[3];

    float* out       = (float*)d_out;
    float* out_res   = out;                                   // B*T*2D
    float* out_align = out + (size_t)B_*T_*2*D_;              // B*N*T
    float* out_max   = out_align + (size_t)B_*N_*T_;          // B*T

    cudaFuncSetAttribute(attn_main, cudaFuncAttributeMaxDynamicSharedMemorySize, SMEM_BYTES);
    dim3 grid(T_/128, B_);
    attn_main<<<grid, NTHREADS, SMEM_BYTES>>>(Q, K, V, prev, out_res, out_align, out_max);
}

// round 13
// speedup vs baseline: 1.4623x; 1.4623x over previous
#include <cuda_runtime.h>
#include <cuda_bf16.h>
#include <cstdint>

#define B_    32
#define T_    1024
#define N_    1024
#define D_    256
#define WIN_  100
#define TT_   64
#define NTHREADS 512

#define KRB  528            // QK bf16 split-buffer row stride (bytes)
#define VROW 528            // V bf16 split row stride (bytes)
#define PROW 272            // P bf16 split row stride (bytes), 16B-aligned
#define PST  65             // prT f32 row stride (floats)

// phase-1 (QK) smem byte offsets
#define OFF_KH 0
#define OFF_KL (OFF_KH + 128*KRB)        //  67584
#define OFF_QH (OFF_KL + 128*KRB)        // 135168
#define OFF_QL (OFF_QH + 64*KRB)         // 168960
// phase-2 aliases (dead after QK MMA)
#define OFF_VH  0
#define OFF_VL  67584
#define OFF_PH  135168
#define OFF_PL  (OFF_PH + 64*PROW)       // 152576
#define OFF_PRT (OFF_PL + 64*PROW)       // 169984
#define SMEM_BYTES (OFF_PRT + 128*PST*4) // 203264

__device__ __forceinline__ uint32_t smem_u32(const void* p) {
    uint32_t a;
    asm("{ .reg .u64 t; cvta.to.shared.u64 t, %1; cvt.u32.u64 %0, t; }" : "=r"(a) : "l"(p));
    return a;
}
__device__ __forceinline__ void ldsm4(uint32_t& r0, uint32_t& r1, uint32_t& r2, uint32_t& r3,
                                      uint32_t addr) {
    asm volatile("ldmatrix.sync.aligned.m8n8.x4.shared.b16 {%0,%1,%2,%3}, [%4];"
                 : "=r"(r0), "=r"(r1), "=r"(r2), "=r"(r3) : "r"(addr));
}
__device__ __forceinline__ void ldsm4t(uint32_t& r0, uint32_t& r1, uint32_t& r2, uint32_t& r3,
                                       uint32_t addr) {
    asm volatile("ldmatrix.sync.aligned.m8n8.x4.trans.shared.b16 {%0,%1,%2,%3}, [%4];"
                 : "=r"(r0), "=r"(r1), "=r"(r2), "=r"(r3) : "r"(addr));
}
__device__ __forceinline__ void mma16816(float* d, const uint32_t* a, uint32_t b0, uint32_t b1) {
    asm volatile("mma.sync.aligned.m16n8k16.row.col.f32.bf16.bf16.f32 "
                 "{%0,%1,%2,%3}, {%4,%5,%6,%7}, {%8,%9}, {%0,%1,%2,%3};"
                 : "+f"(d[0]), "+f"(d[1]), "+f"(d[2]), "+f"(d[3])
                 : "r"(a[0]), "r"(a[1]), "r"(a[2]), "r"(a[3]), "r"(b0), "r"(b1));
}
// packed split: per pair 1 cvt + 2 bitops + 2 subs + 1 cvt (vs ~10 scalar ops)
__device__ __forceinline__ void split8(const float* f, uint32_t* h4, uint32_t* l4) {
    #pragma unroll
    for (int i = 0; i < 4; i++) {
        uint32_t h;
        asm("cvt.rn.bf16x2.f32 %0, %1, %2;" : "=r"(h) : "f"(f[2*i+1]), "f"(f[2*i]));
        float h0 = __uint_as_float(h << 16);            // exact f32 of bf16(lo)
        float h1 = __uint_as_float(h & 0xffff0000u);    // exact f32 of bf16(hi)
        float r0 = f[2*i]   - h0;
        float r1 = f[2*i+1] - h1;
        uint32_t l;
        asm("cvt.rn.bf16x2.f32 %0, %1, %2;" : "=r"(l) : "f"(r1), "f"(r0));
        h4[i] = h;
        l4[i] = l;
    }
}

__global__ __launch_bounds__(NTHREADS, 1)
void attn_main(const float* __restrict__ Q, const float* __restrict__ K,
               const float* __restrict__ V, const int* __restrict__ prev_arr,
               float* __restrict__ out_res, float* __restrict__ out_align,
               float* __restrict__ out_max)
{
    extern __shared__ __align__(128) char sm[];
    const uint32_t smb = smem_u32(sm);
    float* prT = (float*)(sm + OFF_PRT);

    const int b    = blockIdx.y;
    const int t0   = blockIdx.x * TT_;
    const int tid  = threadIdx.x;
    const int warp = tid >> 5;
    const int lane = tid & 31;
    const int prev = prev_arr[b];

    const float* Qb = Q + ((size_t)b*T_ + t0) * D_;
    const float* Kw = K + ((size_t)b*N_ + prev) * D_;
    const float* Vw = V + ((size_t)b*N_ + prev) * D_;

    // ---- Load Q (64x256): out_res Q-half + split-store Qh/Ql ----
    #pragma unroll
    for (int it = 0; it < 4; it++) {
        int idx = tid + NTHREADS * it;
        int t = idx >> 5, g = idx & 31;
        const float* src = Qb + (size_t)t * D_ + 8*g;
        float4 a = *(const float4*)(src);
        float4 c = *(const float4*)(src + 4);
        float f[8] = {a.x,a.y,a.z,a.w,c.x,c.y,c.z,c.w};
        float* qdst = out_res + ((size_t)b*T_ + t0 + t) * (2*D_) + 256 + 8*g;
        *(float4*)(qdst)     = a;
        *(float4*)(qdst + 4) = c;
        uint32_t h4[4], l4[4];
        split8(f, h4, l4);
        uint32_t off = (uint32_t)(t*KRB + 16*g);
        *(uint4*)(sm + OFF_QH + off) = make_uint4(h4[0],h4[1],h4[2],h4[3]);
        *(uint4*)(sm + OFF_QL + off) = make_uint4(l4[0],l4[1],l4[2],l4[3]);
    }
    // ---- Load K (rows 0..99, zero-pad to 128): split-store Kh/Kl ----
    #pragma unroll
    for (int it = 0; it < 8; it++) {
        int idx = tid + NTHREADS * it;
        int j = idx >> 5, g = idx & 31;
        float f[8] = {0,0,0,0,0,0,0,0};
        if (j < WIN_) {
            const float* src = Kw + (size_t)j * D_ + 8*g;
            float4 a = *(const float4*)(src);
            float4 c = *(const float4*)(src + 4);
            f[0]=a.x; f[1]=a.y; f[2]=a.z; f[3]=a.w; f[4]=c.x; f[5]=c.y; f[6]=c.z; f[7]=c.w;
        }
        uint32_t h4[4], l4[4];
        split8(f, h4, l4);
        uint32_t off = (uint32_t)(j*KRB + 16*g);
        *(uint4*)(sm + OFF_KH + off) = make_uint4(h4[0],h4[1],h4[2],h4[3]);
        *(uint4*)(sm + OFF_KL + off) = make_uint4(l4[0],l4[1],l4[2],l4[3]);
    }
    __syncthreads();

    // ============ QK via HMMA: S[64t x 128j]; warp: m-tile=w%4, n-half=w/4 ==========
    const int mi  = warp & 3;
    const int nj0 = (warp >> 2) * 32;
    float dacc[4][4];
    #pragma unroll
    for (int nt = 0; nt < 4; nt++)
        #pragma unroll
        for (int i = 0; i < 4; i++) dacc[nt][i] = 0.f;

    {
        const uint32_t aOff = (uint32_t)((mi*16 + (lane & 15))*KRB + ((lane >> 4) & 1)*16);
        const int nB = nj0 + ((lane >> 4) & 1)*8 + (lane & 7);
        const uint32_t bOff = (uint32_t)(nB*KRB + ((lane >> 3) & 1)*16);
        const uint32_t aQh = smb + OFF_QH + aOff;
        const uint32_t aQl = smb + OFF_QL + aOff;
        const uint32_t bKh0 = smb + OFF_KH + bOff;
        const uint32_t bKl0 = smb + OFF_KL + bOff;

        #pragma unroll 1
        for (int term = 0; term < 3; term++) {
            uint32_t aB  = (term == 2) ? aQl : aQh;
            uint32_t bB0 = (term == 1) ? bKl0 : bKh0;
            uint32_t bB1 = bB0 + 16*KRB;
            #pragma unroll 4
            for (int ks = 0; ks < 16; ks++) {
                uint32_t a[4], b0[4], b1[4];
                ldsm4(a[0], a[1], a[2], a[3], aB + ks*32);
                ldsm4(b0[0], b0[1], b0[2], b0[3], bB0 + ks*32);
                ldsm4(b1[0], b1[1], b1[2], b1[3], bB1 + ks*32);
                mma16816(dacc[0], a, b0[0], b0[1]);
                mma16816(dacc[1], a, b0[2], b0[3]);
                mma16816(dacc[2], a, b1[0], b1[1]);
                mma16816(dacc[3], a, b1[2], b1[3]);
            }
        }
    }
    __syncthreads();   // QK smem reads complete -> aliasing legal

    // ---- Store scores transposed into prT[j][t] (scaled) ----
    {
        const float s = 0.0625f;
        int tb = mi*16 + (lane >> 2);
        int jb = nj0 + (lane & 3)*2;
        #pragma unroll
        for (int nt = 0; nt < 4; nt++) {
            int j = jb + nt*8;
            prT[(j  )*PST + tb    ] = dacc[nt][0] * s;
            prT[(j+1)*PST + tb    ] = dacc[nt][1] * s;
            prT[(j  )*PST + tb + 8] = dacc[nt][2] * s;
            prT[(j+1)*PST + tb + 8] = dacc[nt][3] * s;
        }
    }
    __syncthreads();   // scores visible

    // ============ Phase 3 (warp-specialized) ========================================
    if (warp < 8) {
        // -------- warps 0..7: softmax + argmax + P-split, rows t in [8w, 8w+8) -------
        const int trow = warp * 8;
        #pragma unroll
        for (int tt = 0; tt < 8; tt++) {
            int t = trow + tt;
            float v_[4];
            #pragma unroll
            for (int i = 0; i < 4; i++) v_[i] = prT[(lane + 32*i)*PST + t];

            float mx = -3.4e38f;
            #pragma unroll
            for (int i = 0; i < 4; i++)
                if (lane + 32*i < WIN_) mx = fmaxf(mx, v_[i]);
            #pragma unroll
            for (int off = 16; off; off >>= 1)
                mx = fmaxf(mx, __shfl_xor_sync(0xffffffffu, mx, off));

            float e_[4]; float s = 0.f;
            #pragma unroll
            for (int i = 0; i < 4; i++) {
                e_[i] = (lane + 32*i < WIN_) ? __expf(v_[i] - mx) : 0.f;
                s += e_[i];
            }
            #pragma unroll
            for (int off = 16; off; off >>= 1)
                s += __shfl_xor_sync(0xffffffffu, s, off);
            float inv = 1.f / s;

            float pr[4];
            #pragma unroll
            for (int i = 0; i < 4; i++) pr[i] = e_[i] * inv;

            // first-occurrence argmax over final probs
            float bm = -1.f; int bi = N_;
            #pragma unroll
            for (int i = 0; i < 4; i++)
                if (pr[i] > bm) { bm = pr[i]; bi = lane + 32*i; }
            #pragma unroll
            for (int off = 16; off; off >>= 1) {
                float om = __shfl_xor_sync(0xffffffffu, bm, off);
                int   oi = __shfl_xor_sync(0xffffffffu, bi, off);
                if (om > bm || (om == bm && oi < bi)) { bm = om; bi = oi; }
            }
            if (lane == 0)
                out_max[(size_t)b*T_ + t0 + t] = (float)(prev + bi);

            #pragma unroll
            for (int i = 0; i < 4; i++) {
                int j = lane + 32*i;
                prT[j*PST + t] = pr[i];
                __nv_bfloat16 ph = __float2bfloat16(pr[i]);
                float rl = pr[i] - __bfloat162float(ph);
                __nv_bfloat16 pl = __float2bfloat16(rl);
                *(__nv_bfloat16*)(sm + OFF_PH + t*PROW + 2*j) = ph;
                *(__nv_bfloat16*)(sm + OFF_PL + t*PROW + 2*j) = pl;
            }
        }
    } else {
        // -------- warps 8..15: V load+split (over KH/KL) + alignments zero-fill ------
        const int ltid = tid - 256;    // 0..255
        #pragma unroll
        for (int it = 0; it < 16; it++) {
            int idx = ltid + 256 * it;            // j = idx>>5 in 0..127
            int j = idx >> 5, g = idx & 31;
            float f[8] = {0,0,0,0,0,0,0,0};
            if (j < WIN_) {
                const float* src = Vw + (size_t)j * D_ + 8*g;
                float4 a = *(const float4*)(src);
                float4 c = *(const float4*)(src + 4);
                f[0]=a.x; f[1]=a.y; f[2]=a.z; f[3]=a.w; f[4]=c.x; f[5]=c.y; f[6]=c.z; f[7]=c.w;
            }
            uint32_t h4[4], l4[4];
            split8(f, h4, l4);
            uint32_t off = (uint32_t)(j*VROW + 16*g);
            *(uint4*)(sm + OFF_VH + off) = make_uint4(h4[0],h4[1],h4[2],h4[3]);
            *(uint4*)(sm + OFF_VL + off) = make_uint4(l4[0],l4[1],l4[2],l4[3]);
        }
        // coalesced zero-fill: warp owns rows r = (warp-8), +8, ...; lane -> float2
        #pragma unroll 1
        for (int r = warp - 8; r < N_; r += 8) {
            if (r >= prev && r < prev + WIN_) continue;    // band handled later
            float* ar = out_align + ((size_t)b*N_ + r)*T_ + t0;
            *(float2*)(ar + lane*2) = make_float2(0.f, 0.f);
        }
    }
    __syncthreads();

    // ---- Alignments band rows (coalesced) ----
    #pragma unroll 1
    for (int j = warp; j < WIN_; j += 16) {
        float* ar = out_align + ((size_t)b*N_ + prev + j)*T_ + t0;
        ar[lane]      = prT[j*PST + lane];
        ar[32 + lane] = prT[j*PST + 32 + lane];
    }

    // ================= PV via HMMA: O[64t x 256d] = Ph*Vh + Pl*Vh + Ph*Vl ===========
    {
        const int d0g = (warp >> 2) * 64;
        float oacc[8][4];
        #pragma unroll
        for (int nt = 0; nt < 8; nt++)
            #pragma unroll
            for (int i = 0; i < 4; i++) oacc[nt][i] = 0.f;

        const uint32_t aPOff = (uint32_t)((mi*16 + (lane & 15))*PROW + ((lane >> 4) & 1)*16);
        const uint32_t bVOff = (uint32_t)((lane & 15)*VROW + d0g*2 + ((lane >> 4) & 1)*16);
        const uint32_t aPH = smb + OFF_PH + aPOff;
        const uint32_t aPL = smb + OFF_PL + aPOff;
        const uint32_t bVH = smb + OFF_VH + bVOff;
        const uint32_t bVL = smb + OFF_VL + bVOff;

        #pragma unroll 1
        for (int term = 0; term < 3; term++) {
            uint32_t aB = (term == 2) ? aPL : aPH;
            uint32_t bB = (term == 1) ? bVL : bVH;
            #pragma unroll 2
            for (int ks = 0; ks < 8; ks++) {
                uint32_t a[4];
                ldsm4(a[0], a[1], a[2], a[3], aB + ks*32);
                uint32_t bRow = bB + ks*(16*VROW);
                #pragma unroll
                for (int np = 0; np < 4; np++) {
                    uint32_t bb[4];
                    ldsm4t(bb[0], bb[1], bb[2], bb[3], bRow + np*32);
                    mma16816(oacc[2*np],   a, bb[0], bb[1]);
                    mma16816(oacc[2*np+1], a, bb[2], bb[3]);
                }
            }
        }
        int tr = mi*16 + (lane >> 2);
        int dc = (lane & 3)*2;
        #pragma unroll
        for (int nt = 0; nt < 8; nt++) {
            int d = d0g + nt*8 + dc;
            float* o0 = out_res + ((size_t)b*T_ + t0 + tr    )*(2*D_) + d;
            float* o1 = out_res + ((size_t)b*T_ + t0 + tr + 8)*(2*D_) + d;
            *(float2*)o0 = make_float2(oacc[nt][0], oacc[nt][1]);
            *(float2*)o1 = make_float2(oacc[nt][2], oacc[nt][3]);
        }
    }
}

extern "C" void kernel_launch(void* const* d_in, const int* in_sizes, int n_in,
                              void* d_out, int out_size)
{
    const float* Q    = (const float*)d_in[0];
    const float* K    = (const float*)d_in[1];
    const float* V    = (const float*)d_in[2];
    const int*   prev = (const int*)d_in[3];

    float* out       = (float*)d_out;
    float* out_res   = out;                                   // B*T*2D
    float* out_align = out + (size_t)B_*T_*2*D_;              // B*N*T
    float* out_max   = out_align + (size_t)B_*N_*T_;          // B*T

    cudaFuncSetAttribute(attn_main, cudaFuncAttributeMaxDynamicSharedMemorySize, SMEM_BYTES);
    dim3 grid(T_/TT_, B_);
    attn_main<<<grid, NTHREADS, SMEM_BYTES>>>(Q, K, V, prev, out_res, out_align, out_max);
}